// round 15
// baseline (speedup 1.0000x reference)
#include <cuda_runtime.h>
#include <stdint.h>

#define BATCH  64
#define NIN    784
#define NHID   2048
#define NOUT   10
#define NN     2058
#define NE     262144
#define TSTEPS 30
#define NBLK   148
#define NBACT  147                 // blocks 0..146 own neurons (147*14 = 2058)
#define NTHR   1024
#define WPB    14                  // neurons per block
#define NCLS   (NHID*10)           // 20480 classes (src, delay)
#define CPB    (WPB*10)            // 140 class slots per block
#define ROWW   (NCLS/32)           // 640 words per act row
#define NSLOT  32                  // ring depth
#define CAP    2560

// dynamic smem layout (bytes)
#define SM_EDGE_B (CAP*8)          // 20480
#define SM_ACT_B  (6*ROWW*4)       // 15360
#define SM_DL_B   (CPB*16*4)       // 8960
#define SM_SI_B   (WPB*64*4)       // 3584
#define SM_VEXC_B (2*WPB*64*4)     // 7168
#define SM_INP_B  (WPB*64*4)       // 3584
#define SM_FIRE_B 256
#define SM_CM_B   576
#define SM_MISC_B 64               // rowany[8] + qn
#define SM_Q_B    (CAP*8)          // 20480
#define SMEM_B (SM_EDGE_B+SM_ACT_B+SM_DL_B+SM_SI_B+SM_VEXC_B+SM_INP_B+SM_FIRE_B+SM_CM_B+SM_MISC_B+SM_Q_B)

// ---------------- static device state ----------------
__device__ __align__(16) float    d_val[NSLOT*NCLS*BATCH];  // value ring [slot][cls][b]
__device__ __align__(16) uint32_t d_actb[NSLOT*ROWW];       // act bitmap ring (delivery rows)
__device__ __align__(16) float    d_inp[NHID*BATCH];
__device__ uint32_t d_hist[NN];
__device__ uint32_t d_off[NN+1];
__device__ uint32_t d_cursor[NN];
__device__ __align__(16) uint2    d_edge[NE];               // CSR: {cls | dm6<<21 | pair<<25, w}
__device__ uint32_t d_flags[NBLK];

// ---------------- input GEMM ----------------
__global__ void gemm_kernel(const float* __restrict__ x, const float* __restrict__ W) {
    __shared__ float sx[8*NIN];
    int n  = blockIdx.x * 256 + threadIdx.x;
    int b0 = blockIdx.y * 8;
    for (int i = threadIdx.x; i < 8*NIN; i += 256) {
        int bb = i / NIN, kk = i - bb * NIN;
        sx[bb*NIN + kk] = x[(b0 + bb) * NIN + kk];
    }
    __syncthreads();
    float a[8];
#pragma unroll
    for (int bb = 0; bb < 8; bb++) a[bb] = 0.f;
#pragma unroll 4
    for (int k = 0; k < NIN; k++) {
        float w = W[k * NHID + n];
#pragma unroll
        for (int bb = 0; bb < 8; bb++) a[bb] += sx[bb*NIN + k] * w;
    }
#pragma unroll
    for (int bb = 0; bb < 8; bb++) d_inp[n*64 + b0 + bb] = a[bb];
}

// ---------------- distributed flag grid barrier ----------------
__device__ __forceinline__ void gridbar(uint32_t gen) {
    __syncthreads();
    if (threadIdx.x < 32) {
        __threadfence();
        if (threadIdx.x == 0) __stcg(&d_flags[blockIdx.x], gen);
        bool done = false;
        while (!done) {
            uint32_t mn = 0xFFFFFFFFu;
#pragma unroll
            for (int k = 0; k < 5; k++) {
                int i = threadIdx.x + k * 32;
                uint32_t v = (i < NBLK) ? __ldcg(&d_flags[i]) : 0xFFFFFFFFu;
                mn = min(mn, v);
            }
            done = __all_sync(0xffffffffu, mn >= gen);
            if (!done) __nanosleep(64);
        }
        __threadfence();
    }
    __syncthreads();
}

__device__ __forceinline__ uint32_t spread16(uint32_t x) {
    x &= 0xFFFFu;
    x = (x | (x << 8)) & 0x00FF00FFu;
    x = (x | (x << 4)) & 0x0F0F0F0Fu;
    x = (x | (x << 2)) & 0x33333333u;
    x = (x | (x << 1)) & 0x55555555u;
    return x;
}

// ---------------- launch phase (step u): deadline-based, fired-gated ----------------
__device__ __forceinline__ void launch_phase(int u, int bid,
        const uint32_t* __restrict__ s_cmeta, uint32_t* __restrict__ s_dl,
        const uint32_t* __restrict__ s_fired, const float* __restrict__ s_vexc) {
    int wid = threadIdx.x >> 5, lane = threadIdx.x & 31;
    int sub = lane >> 4, q = lane & 15;
    int wslot = u & (NSLOT-1);
    uint32_t ub = (uint32_t)u * 0x01010101u;
#pragma unroll
    for (int k = 0; k < 3; k++) {
        int cl = k * 64 + wid * 2 + sub;
        bool valid = (cl < CPB);
        int cli = valid ? cl : 0;
        uint32_t cm = s_cmeta[cli];
        valid = valid && (cm != 0xFFFFFFFFu);
        uint32_t nl = cm & 0xFFFFu, d = cm >> 16;
        uint32_t lm = 0u;
        if (valid) {
            uint32_t fw = s_fired[nl*2 + (q >> 3)];
            uint32_t f4 = (fw >> ((q & 7) * 4)) & 15u;
            if (f4) {
                uint32_t fm = ((f4 * 0x00204081u) & 0x01010101u) * 0xFFu;
                uint32_t dl = s_dl[cli*16 + q];
                lm = fm & __vcmpgeu4(ub, dl);
                if (lm)
                    s_dl[cli*16 + q] = (~lm & dl) | (lm & (((uint32_t)u + d + 1u) * 0x01010101u));
            }
        }
        uint32_t bal = __ballot_sync(0xffffffffu, lm != 0u);
        uint32_t halfact = (lane < 16) ? (bal & 0xFFFFu) : (bal >> 16);
        if (valid && halfact) {
            uint32_t cg = (uint32_t)bid * CPB + cl;
            if (q == 0) {
                int row = (u + (int)d) & (NSLOT-1);
                atomicOr(&d_actb[row*ROWW + (cg >> 5)], 1u << (cg & 31u));
            }
            const float4 ve = *(const float4*)&s_vexc[nl*64 + q*4];
            float4 o;
            o.x = (lm & 0x000000FFu) ? ve.x : 0.f;
            o.y = (lm & 0x0000FF00u) ? ve.y : 0.f;
            o.z = (lm & 0x00FF0000u) ? ve.z : 0.f;
            o.w = (lm & 0xFF000000u) ? ve.w : 0.f;
            *(float4*)&d_val[(unsigned)wslot * (NCLS*64) + cg*64 + q*4] = o;
        }
    }
}

// ---------------- persistent simulation kernel ----------------
__global__ void __launch_bounds__(NTHR, 1) sim_kernel(
        const float* __restrict__ We, const float* __restrict__ Le,
        const int* __restrict__ src, const int* __restrict__ tgt,
        float* __restrict__ out) {
    extern __shared__ uint8_t smem[];
    uint2*    s_edge  = (uint2*)smem;
    uint32_t* s_actw  = (uint32_t*)(smem + SM_EDGE_B);
    uint32_t* s_dl    = (uint32_t*)(smem + SM_EDGE_B + SM_ACT_B);
    float*    sI      = (float*)(smem + SM_EDGE_B + SM_ACT_B + SM_DL_B);
    float*    s_vexc  = (float*)(smem + SM_EDGE_B + SM_ACT_B + SM_DL_B + SM_SI_B);
    float*    s_inp   = (float*)(smem + SM_EDGE_B + SM_ACT_B + SM_DL_B + SM_SI_B + SM_VEXC_B);
    uint32_t* s_fired = (uint32_t*)(smem + SM_EDGE_B + SM_ACT_B + SM_DL_B + SM_SI_B + SM_VEXC_B + SM_INP_B);
    uint32_t* s_cmeta = (uint32_t*)(smem + SM_EDGE_B + SM_ACT_B + SM_DL_B + SM_SI_B + SM_VEXC_B + SM_INP_B + SM_FIRE_B);
    uint32_t* s_rowany= (uint32_t*)(smem + SM_EDGE_B + SM_ACT_B + SM_DL_B + SM_SI_B + SM_VEXC_B + SM_INP_B + SM_FIRE_B + SM_CM_B);
    uint32_t* s_qn    = s_rowany + 8;
    uint2*    s_queue = (uint2*)(smem + SM_EDGE_B + SM_ACT_B + SM_DL_B + SM_SI_B + SM_VEXC_B + SM_INP_B + SM_FIRE_B + SM_CM_B + SM_MISC_B);

    int tid = threadIdx.x;
    int bid = blockIdx.x;
    int gtid = bid * NTHR + tid;
    int n0 = bid * WPB;
    uint32_t base = __ldcg(&d_flags[bid]);

    for (int i = tid; i < CPB*16; i += NTHR) s_dl[i] = 0u;   // deadline 0 -> eligible
    if (tid < WPB*64) sI[tid] = 0.f;
    if (tid == 0) *s_qn = 0u;
    if (tid < CPB) {
        int nl = tid / 10, d = tid % 10 + 6;
        bool v = (bid < NBACT) && (n0 + nl < NHID);
        s_cmeta[tid] = v ? ((uint32_t)nl | ((uint32_t)d << 16)) : 0xFFFFFFFFu;
    }

    // ---- 0. zero act ring + hist ----
    for (int i = gtid; i < NSLOT*ROWW; i += NBLK*NTHR) d_actb[i] = 0u;
    for (int i = gtid; i < NN; i += NBLK*NTHR) d_hist[i] = 0u;
    gridbar(base + 1);

    // ---- 1. histogram over targets ----
    for (int e = gtid; e < NE; e += NBLK*NTHR)
        atomicAdd(&d_hist[tgt[e]], 1u);
    gridbar(base + 2);

    // ---- 2. scan (block 0), scratch = s_edge ----
    if (bid == 0) {
        uint32_t* sa = (uint32_t*)s_edge;
        uint32_t* sb = sa + NN;
        for (int i = tid; i < NN; i += NTHR) sa[i] = d_hist[i];
        __syncthreads();
        uint32_t *pin = sa, *pout = sb;
        for (int off = 1; off < NN; off <<= 1) {
            for (int i = tid; i < NN; i += NTHR)
                pout[i] = pin[i] + (i >= off ? pin[i - off] : 0u);
            __syncthreads();
            uint32_t* t = pin; pin = pout; pout = t;
        }
        for (int i = tid; i < NN; i += NTHR) {
            d_off[i+1]  = pin[i];
            d_cursor[i] = (i > 0) ? pin[i-1] : 0u;
        }
        if (tid == 0) d_off[0] = 0u;
        __syncthreads();
    }
    gridbar(base + 3);

    // ---- 3. scatter into CSR (embed local target pair in bits 25..28) ----
    for (int e = gtid; e < NE; e += NBLK*NTHR) {
        uint32_t dm6 = (uint32_t)(int)(Le[e] * 2.0f + 0.5f) - 6u;   // 0..9
        uint32_t s = (uint32_t)src[e];
        uint32_t t = (uint32_t)tgt[e];
        uint32_t pos = atomicAdd(&d_cursor[t], 1u);
        d_edge[pos] = make_uint2((s*10u + dm6) | (dm6 << 21) | ((t % WPB) << 25),
                                 __float_as_uint(We[e]));
    }
    gridbar(base + 4);

    // ---- 4. stage CSR segment + inp ----
    int blockBeg = 0; bool fits = false; int total = 0;
    int hidcnt = 0;
    if (bid < NBACT) {
        hidcnt = (n0 < NHID) ? min(WPB, NHID - n0) : 0;
        int nEnd = n0 + WPB; if (nEnd > NN) nEnd = NN;
        blockBeg = d_off[n0];
        total = d_off[nEnd] - blockBeg;
        fits = (total <= CAP);
        if (fits)
            for (int i = tid; i < total; i += NTHR)
                s_edge[i] = __ldg(&d_edge[blockBeg + i]);
        if (tid < hidcnt*64) s_inp[tid] = d_inp[n0*64 + tid];
    }
    __syncthreads();

    int wid = tid >> 5, lane = tid & 31;
    int n = n0 + wid;                      // warp wid < WPB owns neuron n
    bool nvalid = (bid < NBACT) && (wid < WPB) && (n < NN);

    // act-clear geometry (class range [cc0, cc1))
    int cc0 = bid * CPB;
    int cc1 = cc0 + hidcnt * 10;
    int cw0 = cc0 >> 5;
    int cnw = (cc1 > cc0) ? ((cc1 - 1) >> 5) - cw0 + 1 : 0;

    int T = (total + 31) >> 5;             // 32-edge tiles
    float vm0 = 0.f, vm1 = 0.f, acc0 = 0.f, acc1 = 0.f;

    // ---- simulation: 5 regions x 6 steps ----
    for (int r = 0; r < 5; r++) {
        int u0 = r * 6;
        gridbar(base + 5 + r);
        if (tid < 6) s_rowany[tid] = 0u;
        __syncthreads();
        if (bid < NBACT) {
            for (int i = tid; i < 6*ROWW; i += NTHR) {
                int j = i / ROWW, w = i - j*ROWW;
                uint32_t v = __ldcg(&d_actb[((u0 + j) & (NSLOT-1))*ROWW + w]);
                s_actw[i] = v;
                if (v) s_rowany[j] = 1u;      // benign race
            }
            if (tid < 6*cnw) {
                int j = tid / cnw, k = tid - j*cnw;
                int w = cw0 + k;
                int lo = cc0 - w*32; if (lo < 0) lo = 0;
                int hi = cc1 - w*32; if (hi > 32) hi = 32;
                uint32_t mask = ((hi >= 32) ? 0xFFFFFFFFu : ((1u << hi) - 1u))
                                & ~((lo <= 0) ? 0u : ((1u << lo) - 1u));
                int row = (u0 - 12 + j + 2*NSLOT) & (NSLOT-1);
                atomicAnd(&d_actb[row*ROWW + w], ~mask);
            }
        }
        __syncthreads();

        for (int j = 0; j < 6; j++) {
            int u = u0 + j;
            int buf = u & 1;
            const uint32_t* actrow = s_actw + j*ROWW;
            bool rowact = (bid < NBACT) && (s_rowany[j] != 0u);
            uint32_t uu = (uint32_t)(u - 6);

            // ---- filter: all warps tile the block edge list into the queue ----
            if (rowact) {
                if (fits) {
                    for (int t = wid; t < T; t += 32) {
                        int e = t*32 + lane;
                        bool pass = false;
                        uint2 ed;
                        if (e < total) {
                            ed = s_edge[e];
                            uint32_t cls = ed.x & 0x7FFFu;
                            pass = (actrow[cls >> 5] >> (cls & 31u)) & 1u;
                        }
                        uint32_t bal = __ballot_sync(0xffffffffu, pass);
                        int np = __popc(bal);
                        uint32_t qb = 0u;
                        if (lane == 0 && np) qb = atomicAdd(s_qn, (uint32_t)np);
                        qb = __shfl_sync(0xffffffffu, qb, 0);
                        if (pass) {
                            uint32_t cls = ed.x & 0x7FFFu;
                            uint32_t dm6 = (ed.x >> 21) & 15u;
                            uint32_t slot = (uu - dm6) & (NSLOT-1u);
                            uint32_t pr  = ed.x >> 25;
                            int pos = qb + __popc(bal & ((1u << lane) - 1u));
                            s_queue[pos] = make_uint2((slot*NCLS + cls) | (pr << 20), ed.y);
                        }
                    }
                } else {
                    // fallback: immediate consume from global CSR (rare)
                    for (int t = wid; t < T; t += 32) {
                        int e = t*32 + lane;
                        if (e < total) {
                            uint2 ed = __ldg(&d_edge[blockBeg + e]);
                            uint32_t cls = ed.x & 0x7FFFu;
                            if ((actrow[cls >> 5] >> (cls & 31u)) & 1u) {
                                uint32_t dm6 = (ed.x >> 21) & 15u;
                                uint32_t slot = (uu - dm6) & (NSLOT-1u);
                                uint32_t pr  = ed.x >> 25;
                                float w = __uint_as_float(ed.y);
                                const float* vb = d_val + (slot*NCLS + cls)*64;
                                // lane-serial over 64 batches (slow path, never expected)
                                for (int b = 0; b < 64; b++)
                                    atomicAdd(&sI[pr*64 + b], w * __ldg(vb + b));
                            }
                        }
                    }
                }
            }
            __syncthreads();                              // F: queue complete
            if (rowact && fits) {
                int M = (int)*s_qn;
                for (int t = wid; t < M; t += 32) {
                    uint2 en = s_queue[t];
                    uint32_t pr = en.x >> 20;
                    float w = __uint_as_float(en.y);
                    float2 v = __ldg((const float2*)(d_val + (en.x & 0xFFFFFu)*64 + 2*lane));
                    atomicAdd(&sI[pr*64 + 2*lane],     w * v.x);
                    atomicAdd(&sI[pr*64 + 2*lane + 1], w * v.y);
                }
            }
            __syncthreads();                              // A: sI complete
            if (nvalid) {
                float I0 = sI[wid*64 + 2*lane];
                float I1 = sI[wid*64 + 2*lane + 1];
                sI[wid*64 + 2*lane]     = 0.f;
                sI[wid*64 + 2*lane + 1] = 0.f;
                bool hid = n < NHID;
                if (hid && (u % 3) == 2) {
                    float2 ip = *(const float2*)&s_inp[wid*64 + 2*lane];
                    I0 += ip.x; I1 += ip.y;
                }
                vm0 += (I0 - vm0) * 0.1f;
                vm1 += (I1 - vm1) * 0.1f;
                if (!hid) { acc0 += vm0; acc1 += vm1; }
                else {
                    float ve0 = fmaxf(0.f, vm0 - 0.25f);
                    float ve1 = fmaxf(0.f, vm1 - 0.25f);
                    bool f0 = ve0 > 0.f, f1 = ve1 > 0.f;
                    if (f0) vm0 = -0.2f;
                    if (f1) vm1 = -0.2f;
                    *(float2*)&s_vexc[buf*WPB*64 + wid*64 + 2*lane] = make_float2(ve0, ve1);
                    uint32_t b0 = __ballot_sync(0xffffffffu, f0);
                    uint32_t b1 = __ballot_sync(0xffffffffu, f1);
                    uint32_t w0 = spread16(b0 & 0xFFFFu) | (spread16(b1 & 0xFFFFu) << 1);
                    uint32_t w1 = spread16(b0 >> 16)     | (spread16(b1 >> 16) << 1);
                    if (lane == 0) s_fired[buf*WPB*2 + wid*2]     = w0;
                    if (lane == 1) s_fired[buf*WPB*2 + wid*2 + 1] = w1;
                }
            }
            if (tid == NTHR-1) *s_qn = 0u;                // reset for next step
            __syncthreads();                              // B
            if (bid < NBACT)
                launch_phase(u, bid, s_cmeta, s_dl,
                             s_fired + buf*WPB*2, s_vexc + buf*WPB*64);
            // parity buffering: launch(u) reads buf u&1; neuron(u+1) writes buf (u+1)&1
        }
    }

    if (nvalid && n >= NHID) {
        int o = n - NHID;
        out[(2*lane)   * NOUT + o] = acc0 * (1.0f / (float)TSTEPS);
        out[(2*lane+1) * NOUT + o] = acc1 * (1.0f / (float)TSTEPS);
    }
}

extern "C" void kernel_launch(void* const* d_in, const int* in_sizes, int n_in,
                              void* d_out, int out_size) {
    const float* x   = (const float*)d_in[0];
    const float* W   = (const float*)d_in[1];
    const float* We  = (const float*)d_in[2];
    const float* Le  = (const float*)d_in[3];
    const int*   src = (const int*)d_in[4];
    const int*   tgt = (const int*)d_in[5];
    float* out = (float*)d_out;
    (void)in_sizes; (void)n_in; (void)out_size;

    cudaFuncSetAttribute(sim_kernel, cudaFuncAttributeMaxDynamicSharedMemorySize, SMEM_B);
    dim3 gg(8, 8);
    gemm_kernel<<<gg, 256>>>(x, W);
    sim_kernel<<<NBLK, NTHR, SMEM_B>>>(We, Le, src, tgt, out);
}

// round 17
// speedup vs baseline: 1.5715x; 1.5715x over previous
#include <cuda_runtime.h>
#include <stdint.h>

#define BATCH  64
#define NIN    784
#define NHID   2048
#define NOUT   10
#define NN     2058
#define NE     262144
#define TSTEPS 30
#define NBLK   296
#define NBACT  294                 // blocks 0..293 own neurons (294*7 = 2058)
#define NTHR   512
#define WPB    7                   // neurons per block
#define NCLS   (NHID*10)           // 20480 classes (src, delay)
#define CPB    (WPB*10)            // 70 class slots per block
#define ROWW   (NCLS/32)           // 640 words per act row
#define NSLOT  32                  // ring depth
#define CAP    1536
#define BK     256                 // bucket slots per target
#define BCAP   112                 // filter bucket entries per warp

// dynamic smem layout (bytes)
#define SM_EDGE_B (CAP*8)          // 12288
#define SM_ACT_B  (6*ROWW*4)       // 15360
#define SM_DL_B   (CPB*16*4)       // 4480
#define SM_PART_B 2048
#define SM_VEXC_B (2*WPB*64*4)     // 3584
#define SM_INP_B  2048
#define SM_FIRE_B 128
#define SM_CM_B   320
#define SM_MISC_B 64               // rowany[6] + begs[8]
#define SM_BUCK_B (16*BCAP*8)      // 14336
#define SM_FIX_B (SM_EDGE_B+SM_ACT_B+SM_DL_B+SM_PART_B+SM_VEXC_B+SM_INP_B+SM_FIRE_B+SM_CM_B+SM_MISC_B+SM_BUCK_B)
#define SM_GEMM_B (112*65*4)       // 29120 gemm scratch (overlays edge/act head)
#define SMEM_B ((SM_FIX_B > SM_GEMM_B) ? SM_FIX_B : SM_GEMM_B)   // 54656

// ---------------- static device state ----------------
__device__ __align__(16) float    d_val[NSLOT*NCLS*BATCH];  // value ring [slot][cls][b]
__device__ __align__(16) uint32_t d_actb[NSLOT*ROWW];       // act bitmap ring
__device__ uint32_t d_cnt[NN];                              // per-target degree
__device__ __align__(16) uint2    d_bucket[NN*BK];          // {cls | dm6<<21 | pr<<25, w}
__device__ uint32_t d_flags[NBLK];

// ---------------- distributed flag grid barrier ----------------
__device__ __forceinline__ void gridbar(uint32_t gen) {
    __syncthreads();
    if (threadIdx.x < 32) {
        __threadfence();
        if (threadIdx.x == 0) __stcg(&d_flags[blockIdx.x], gen);
        bool done = false;
        while (!done) {
            uint32_t mn = 0xFFFFFFFFu;
#pragma unroll
            for (int k = 0; k < 10; k++) {
                int i = threadIdx.x + k * 32;
                uint32_t v = (i < NBLK) ? __ldcg(&d_flags[i]) : 0xFFFFFFFFu;
                mn = min(mn, v);
            }
            done = __all_sync(0xffffffffu, mn >= gen);
            if (!done) __nanosleep(64);
        }
        __threadfence();
    }
    __syncthreads();
}

__device__ __forceinline__ uint32_t spread16(uint32_t x) {
    x &= 0xFFFFu;
    x = (x | (x << 8)) & 0x00FF00FFu;
    x = (x | (x << 4)) & 0x0F0F0F0Fu;
    x = (x | (x << 2)) & 0x33333333u;
    x = (x | (x << 1)) & 0x55555555u;
    return x;
}

// ---------------- launch phase (step u): deadline-based, fired-gated ----------------
__device__ __forceinline__ void launch_phase(int u, int bid,
        const uint32_t* __restrict__ s_cmeta, uint32_t* __restrict__ s_dl,
        const uint32_t* __restrict__ s_fired, const float* __restrict__ s_vexc) {
    int wid = threadIdx.x >> 5, lane = threadIdx.x & 31;
    int sub = lane >> 4, q = lane & 15;
    int wslot = u & (NSLOT-1);
    uint32_t ub = (uint32_t)u * 0x01010101u;
#pragma unroll
    for (int k = 0; k < 3; k++) {
        int cl = k * 32 + wid * 2 + sub;
        bool valid = (cl < CPB);
        int cli = valid ? cl : 0;
        uint32_t cm = s_cmeta[cli];
        valid = valid && (cm != 0xFFFFFFFFu);
        uint32_t nl = cm & 0xFFFFu, d = cm >> 16;
        uint32_t lm = 0u;
        if (valid) {
            uint32_t fw = s_fired[nl*2 + (q >> 3)];
            uint32_t f4 = (fw >> ((q & 7) * 4)) & 15u;
            if (f4) {
                uint32_t fm = ((f4 * 0x00204081u) & 0x01010101u) * 0xFFu;
                uint32_t dl = s_dl[cli*16 + q];
                lm = fm & __vcmpgeu4(ub, dl);
                if (lm)
                    s_dl[cli*16 + q] = (~lm & dl) | (lm & (((uint32_t)u + d + 1u) * 0x01010101u));
            }
        }
        uint32_t bal = __ballot_sync(0xffffffffu, lm != 0u);
        uint32_t halfact = (lane < 16) ? (bal & 0xFFFFu) : (bal >> 16);
        if (valid && halfact) {
            uint32_t cg = ((uint32_t)bid * WPB + nl) * 10u + (d - 6u);
            if (q == 0) {
                int row = (u + (int)d) & (NSLOT-1);
                atomicOr(&d_actb[row*ROWW + (cg >> 5)], 1u << (cg & 31u));
            }
            const float4 ve = *(const float4*)&s_vexc[nl*64 + q*4];
            float4 o;
            o.x = (lm & 0x000000FFu) ? ve.x : 0.f;
            o.y = (lm & 0x0000FF00u) ? ve.y : 0.f;
            o.z = (lm & 0x00FF0000u) ? ve.z : 0.f;
            o.w = (lm & 0xFF000000u) ? ve.w : 0.f;
            *(float4*)&d_val[(unsigned)wslot * (NCLS*64) + cg*64 + q*4] = o;
        }
    }
}

// ---------------- fallback consumer body ----------------
#define EDGE_BODY(ED)                                                            \
    {                                                                            \
        uint32_t cls = (ED).x & 0x7FFFu;                                         \
        if ((actrow[cls >> 5] >> (cls & 31u)) & 1u) {                            \
            uint32_t dm6 = ((ED).x >> 21) & 15u;                                 \
            uint32_t slot = (uu - dm6) & (NSLOT-1u);                             \
            float w = __uint_as_float((ED).y);                                   \
            float2 v = __ldg((const float2*)(valbase + slot*(NCLS*64) + cls*64)); \
            I0 += w * v.x;                                                       \
            I1 += w * v.y;                                                       \
        }                                                                        \
    }

// ---------------- warp-parallel filter + compact consume ----------------
__device__ __forceinline__ void filter_consume(int u, int i0, int i1, int gbase, bool fits,
        const uint2* __restrict__ s_edge, const uint32_t* __restrict__ actrow,
        uint2* __restrict__ buck, float& I0, float& I1) {
    int lane = threadIdx.x & 31;
    const float* valbase = d_val + 2*lane;
    uint32_t uu = (uint32_t)(u - 6);
    int cnt = i1 - i0;
    if (cnt <= 0) return;
    if (cnt <= BCAP) {
        int m = 0;
        for (int i = i0; i < i1; i += 32) {
            int e = i + lane;
            bool pass = false;
            uint2 ed = make_uint2(0u, 0u);
            if (e < i1) {
                ed = fits ? s_edge[e] : __ldg(&d_bucket[gbase + e]);
                uint32_t cls = ed.x & 0x7FFFu;
                pass = (actrow[cls >> 5] >> (cls & 31u)) & 1u;
            }
            uint32_t bal = __ballot_sync(0xffffffffu, pass);
            if (pass) {
                uint32_t cls = ed.x & 0x7FFFu;
                uint32_t dm6 = (ed.x >> 21) & 15u;
                uint32_t slot = (uu - dm6) & (NSLOT-1u);
                int pos = m + __popc(bal & ((1u << lane) - 1u));
                buck[pos] = make_uint2(slot*(NCLS*64u) + cls*64u, ed.y);
            }
            m += __popc(bal);
        }
#pragma unroll 4
        for (int t = 0; t < m; t++) {
            uint2 en = buck[t];
            float w = __uint_as_float(en.y);
            float2 v = __ldg((const float2*)(valbase + en.x));
            I0 += w * v.x;
            I1 += w * v.y;
        }
    } else {
        if (fits) {
#pragma unroll 8
            for (int i = i0; i < i1; i++) { uint2 ed = s_edge[i]; EDGE_BODY(ed) }
        } else {
#pragma unroll 8
            for (int i = i0; i < i1; i++) { uint2 ed = __ldg(&d_bucket[gbase + i]); EDGE_BODY(ed) }
        }
    }
}

// ---------------- persistent simulation kernel ----------------
__global__ void __launch_bounds__(NTHR, 2) sim_kernel(
        const float* __restrict__ x,  const float* __restrict__ W,
        const float* __restrict__ We, const float* __restrict__ Le,
        const int* __restrict__ src,  const int* __restrict__ tgt,
        float* __restrict__ out) {
    extern __shared__ uint8_t smem[];
    uint2*    s_edge  = (uint2*)smem;
    uint32_t* s_actw  = (uint32_t*)(smem + SM_EDGE_B);
    uint32_t* s_dl    = (uint32_t*)(smem + SM_EDGE_B + SM_ACT_B);
    float2*   s_part  = (float2*)(smem + SM_EDGE_B + SM_ACT_B + SM_DL_B);
    float*    s_vexc  = (float*)(smem + SM_EDGE_B + SM_ACT_B + SM_DL_B + SM_PART_B);
    float*    s_inp   = (float*)(smem + SM_EDGE_B + SM_ACT_B + SM_DL_B + SM_PART_B + SM_VEXC_B);
    uint32_t* s_fired = (uint32_t*)(smem + SM_EDGE_B + SM_ACT_B + SM_DL_B + SM_PART_B + SM_VEXC_B + SM_INP_B);
    uint32_t* s_cmeta = (uint32_t*)(smem + SM_EDGE_B + SM_ACT_B + SM_DL_B + SM_PART_B + SM_VEXC_B + SM_INP_B + SM_FIRE_B);
    uint32_t* s_rowany= (uint32_t*)(smem + SM_EDGE_B + SM_ACT_B + SM_DL_B + SM_PART_B + SM_VEXC_B + SM_INP_B + SM_FIRE_B + SM_CM_B);
    uint32_t* s_begs  = s_rowany + 6;                       // [8]
    uint2*    s_buck  = (uint2*)(smem + SM_EDGE_B + SM_ACT_B + SM_DL_B + SM_PART_B + SM_VEXC_B + SM_INP_B + SM_FIRE_B + SM_CM_B + SM_MISC_B);
    float*    s_xT    = (float*)smem;                       // gemm scratch (overlays head)

    int tid = threadIdx.x;
    int bid = blockIdx.x;
    int gtid = bid * NTHR + tid;
    int n0 = bid * WPB;
    uint32_t base = __ldcg(&d_flags[bid]);
    int hidcnt = (bid < NBACT && n0 < NHID) ? min(WPB, NHID - n0) : 0;

    // ---- 0. zero act ring + cnt ----
    for (int i = gtid; i < NSLOT*ROWW; i += NBLK*NTHR) d_actb[i] = 0u;
    for (int i = gtid; i < NN; i += NBLK*NTHR) d_cnt[i] = 0u;
    gridbar(base + 1);

    // ---- 1. scatter into per-target buckets ----
    for (int e = gtid; e < NE; e += NBLK*NTHR) {
        uint32_t dm6 = (uint32_t)(int)(Le[e] * 2.0f + 0.5f) - 6u;   // 0..9
        uint32_t s = (uint32_t)src[e];
        uint32_t t = (uint32_t)tgt[e];
        uint32_t pos = atomicAdd(&d_cnt[t], 1u);
        d_bucket[t*BK + pos] = make_uint2((s*10u + dm6) | (dm6 << 21) | ((t % WPB) << 25),
                                          __float_as_uint(We[e]));
    }

    // ---- 2. input GEMM for own hidden neurons -> register (uses smem scratch) ----
    float inp_acc = 0.f;
    {
        int nl = tid >> 6, b = tid & 63;
        bool gv = (nl < hidcnt);
        int nn = n0 + nl;
        for (int c = 0; c < 7; c++) {
            __syncthreads();
            for (int i = tid; i < 112*64; i += NTHR) {
                int bb = i / 112, kk = i - bb*112;
                s_xT[kk*65 + bb] = x[bb*NIN + c*112 + kk];
            }
            __syncthreads();
            if (gv) {
#pragma unroll 4
                for (int k = 0; k < 112; k++)
                    inp_acc += s_xT[k*65 + b] * W[(c*112 + k)*NHID + nn];
            }
        }
        __syncthreads();
    }
    // smem scratch now free; build persistent smem structures
    for (int i = tid; i < CPB*16; i += NTHR) s_dl[i] = 0u;
    if (tid < CPB) {
        int nl = tid / 10, d = tid % 10 + 6;
        bool v = (nl < hidcnt);
        s_cmeta[tid] = v ? ((uint32_t)nl | ((uint32_t)d << 16)) : 0xFFFFFFFFu;
    }
    if (tid < WPB*64) s_inp[tid] = 0.f;
    __syncthreads();
    if (tid < WPB*64 && (tid >> 6) < hidcnt) s_inp[tid] = inp_acc;
    gridbar(base + 2);

    // ---- 3. stage edges from buckets ----
    int total = 0; bool fits = false;
    if (bid < NBACT) {
        if (tid == 0) {
            uint32_t acc = 0u;
            s_begs[0] = 0u;
            for (int nl = 0; nl < WPB; nl++) {
                int nn = n0 + nl;
                acc += (nn < NN) ? __ldcg(&d_cnt[nn]) : 0u;
                s_begs[nl+1] = acc;
            }
        }
        __syncthreads();
        total = (int)s_begs[WPB];
        fits = (total <= CAP);
        if (fits) {
            for (int nl = 0; nl < WPB; nl++) {
                int nn = n0 + nl;
                if (nn >= NN) break;
                int beg = (int)s_begs[nl], deg = (int)s_begs[nl+1] - beg;
                for (int i = tid; i < deg; i += NTHR)
                    s_edge[beg + i] = __ldg(&d_bucket[nn*BK + i]);
            }
        }
    }
    __syncthreads();

    int wid = tid >> 5, lane = tid & 31;
    int pair = wid >> 1, half = wid & 1;
    int n = n0 + pair;
    bool nvalid = (bid < NBACT) && (pair < WPB) && (n < NN);
    int cnt = 0, lbeg = 0, gbase = 0;
    if (nvalid) {
        lbeg = (int)s_begs[pair];
        cnt = (int)s_begs[pair+1] - lbeg;
        gbase = n * BK;
    }
    int h0 = cnt >> 1;
    int i0 = half ? h0 : 0;
    int i1 = half ? cnt : h0;
    uint2* mybuck = s_buck + wid * BCAP;

    // act-clear geometry (class range [cc0, cc1))
    int cc0 = bid * CPB;
    int cc1 = cc0 + hidcnt * 10;
    int cw0 = cc0 >> 5;
    int cnw = (cc1 > cc0) ? ((cc1 - 1) >> 5) - cw0 + 1 : 0;

    float vm0 = 0.f, vm1 = 0.f, acc0 = 0.f, acc1 = 0.f;

    // ---- simulation: 5 regions x 6 steps ----
    for (int r = 0; r < 5; r++) {
        int u0 = r * 6;
        gridbar(base + 3 + r);
        if (tid < 6) s_rowany[tid] = 0u;
        __syncthreads();
        if (bid < NBACT) {
            for (int i = tid; i < 6*ROWW; i += NTHR) {
                int j = i / ROWW, w = i - j*ROWW;
                uint32_t v = __ldcg(&d_actb[((u0 + j) & (NSLOT-1))*ROWW + w]);
                s_actw[i] = v;
                if (v) s_rowany[j] = 1u;      // benign race
            }
            if (tid < 6*cnw) {
                int j = tid / cnw, k = tid - j*cnw;
                int w = cw0 + k;
                int lo = cc0 - w*32; if (lo < 0) lo = 0;
                int hi = cc1 - w*32; if (hi > 32) hi = 32;
                uint32_t mask = ((hi >= 32) ? 0xFFFFFFFFu : ((1u << hi) - 1u))
                                & ~((lo <= 0) ? 0u : ((1u << lo) - 1u));
                int row = (u0 - 12 + j + 2*NSLOT) & (NSLOT-1);
                atomicAnd(&d_actb[row*ROWW + w], ~mask);
            }
        }
        __syncthreads();

        for (int j = 0; j < 6; j++) {
            int u = u0 + j;
            int buf = u & 1;
            const uint32_t* actrow = s_actw + j*ROWW;
            bool rowact = (bid < NBACT) && (s_rowany[j] != 0u);
            float I0 = 0.f, I1 = 0.f;
            if (rowact && nvalid)
                filter_consume(u, fits ? (lbeg + i0) : i0, fits ? (lbeg + i1) : i1,
                               gbase, fits, s_edge, actrow, mybuck, I0, I1);
            if (half == 1 && nvalid) s_part[pair*32 + lane] = make_float2(I0, I1);
            __syncthreads();                              // A
            if (nvalid && half == 0) {
                float2 p = s_part[pair*32 + lane];
                I0 += p.x; I1 += p.y;
                bool hid = n < NHID;
                if (hid && (u % 3) == 2) {
                    float2 ip = *(const float2*)&s_inp[pair*64 + 2*lane];
                    I0 += ip.x; I1 += ip.y;
                }
                vm0 += (I0 - vm0) * 0.1f;
                vm1 += (I1 - vm1) * 0.1f;
                if (!hid) { acc0 += vm0; acc1 += vm1; }
                else {
                    float ve0 = fmaxf(0.f, vm0 - 0.25f);
                    float ve1 = fmaxf(0.f, vm1 - 0.25f);
                    bool f0 = ve0 > 0.f, f1 = ve1 > 0.f;
                    if (f0) vm0 = -0.2f;
                    if (f1) vm1 = -0.2f;
                    *(float2*)&s_vexc[buf*WPB*64 + pair*64 + 2*lane] = make_float2(ve0, ve1);
                    uint32_t b0 = __ballot_sync(0xffffffffu, f0);
                    uint32_t b1 = __ballot_sync(0xffffffffu, f1);
                    uint32_t w0 = spread16(b0 & 0xFFFFu) | (spread16(b1 & 0xFFFFu) << 1);
                    uint32_t w1 = spread16(b0 >> 16)     | (spread16(b1 >> 16) << 1);
                    if (lane == 0) s_fired[buf*WPB*2 + pair*2]     = w0;
                    if (lane == 1) s_fired[buf*WPB*2 + pair*2 + 1] = w1;
                }
            } else if (half == 0) {
                __ballot_sync(0xffffffffu, false);
                __ballot_sync(0xffffffffu, false);
            }
            __syncthreads();                              // B
            if (bid < NBACT)
                launch_phase(u, bid, s_cmeta, s_dl,
                             s_fired + buf*WPB*2, s_vexc + buf*WPB*64);
            // parity buffering: launch(u) reads buf u&1; neuron(u+1) writes buf (u+1)&1
        }
    }

    if (nvalid && half == 0 && n >= NHID) {
        int o = n - NHID;
        out[(2*lane)   * NOUT + o] = acc0 * (1.0f / (float)TSTEPS);
        out[(2*lane+1) * NOUT + o] = acc1 * (1.0f / (float)TSTEPS);
    }
}

extern "C" void kernel_launch(void* const* d_in, const int* in_sizes, int n_in,
                              void* d_out, int out_size) {
    const float* x   = (const float*)d_in[0];
    const float* W   = (const float*)d_in[1];
    const float* We  = (const float*)d_in[2];
    const float* Le  = (const float*)d_in[3];
    const int*   src = (const int*)d_in[4];
    const int*   tgt = (const int*)d_in[5];
    float* out = (float*)d_out;
    (void)in_sizes; (void)n_in; (void)out_size;

    cudaFuncSetAttribute(sim_kernel, cudaFuncAttributeMaxDynamicSharedMemorySize, SMEM_B);
    sim_kernel<<<NBLK, NTHR, SMEM_B>>>(x, W, We, Le, src, tgt, out);
}